// round 2
// baseline (speedup 1.0000x reference)
#include <cuda_runtime.h>
#include <cuda_bf16.h>
#include <cstdint>
#include <cstddef>

#define B_ROWS 4096
#define D_DIM  1024
#define N2     8192        // 2B
#define INV_T  2.0f        // 1/temperature

// Scratch (device globals; no allocation allowed)
__device__ __nv_bfloat16 g_reps[(size_t)N2 * D_DIM];   // normalized reps, bf16
__device__ float         g_rowsum[N2];                 // sum_{c != r} exp(sim[r][c]/T)

// ---------------------------------------------------------------------------
// Kernel 1: L2-normalize rows of emb_i / emb_j into bf16 reps; zero accumulators
// ---------------------------------------------------------------------------
__global__ void normalize_kernel(const float* __restrict__ emb_i,
                                 const float* __restrict__ emb_j,
                                 float* __restrict__ out)
{
    int row = blockIdx.x;                       // 0..8191
    const float* src = (row < B_ROWS) ? (emb_i + (size_t)row * D_DIM)
                                      : (emb_j + (size_t)(row - B_ROWS) * D_DIM);
    int t = threadIdx.x;                        // 256 threads, 4 floats each
    float4 v = ((const float4*)src)[t];
    float ss = v.x * v.x + v.y * v.y + v.z * v.z + v.w * v.w;

    #pragma unroll
    for (int o = 16; o; o >>= 1) ss += __shfl_xor_sync(0xFFFFFFFFu, ss, o);

    __shared__ float warp_ss[8];
    if ((t & 31) == 0) warp_ss[t >> 5] = ss;
    __syncthreads();
    if (t < 32) {
        float s = (t < 8) ? warp_ss[t] : 0.0f;
        #pragma unroll
        for (int o = 4; o; o >>= 1) s += __shfl_xor_sync(0xFFFFFFFFu, s, o);
        if (t == 0) warp_ss[0] = s;
    }
    __syncthreads();

    float norm = sqrtf(warp_ss[0]);
    float rinv = 1.0f / fmaxf(norm, 1e-12f);

    __nv_bfloat162* dst = (__nv_bfloat162*)(g_reps + (size_t)row * D_DIM);
    dst[t * 2 + 0] = __float22bfloat162_rn(make_float2(v.x * rinv, v.y * rinv));
    dst[t * 2 + 1] = __float22bfloat162_rn(make_float2(v.z * rinv, v.w * rinv));

    // zero rowsum (8192 floats) and output scalar
    if (blockIdx.x < 32) g_rowsum[blockIdx.x * 256 + t] = 0.0f;
    if (blockIdx.x == 0 && t == 0) out[0] = 0.0f;
}

// ---------------------------------------------------------------------------
// Kernel 2: fused  exp(2 * Z Z^T)  row-sum with diagonal mask.
// CTA tile 128x128, BK=32, 8 warps (2 x 4), warp tile 64x32, mma.m16n8k16 bf16.
// ---------------------------------------------------------------------------
#define BK    32
#define SSTR  48   // padded smem row stride (bf16 elems); 96B rows, 16B aligned

__global__ __launch_bounds__(256, 2)
void simexp_kernel()
{
    __shared__ __nv_bfloat16 sA[128 * SSTR];
    __shared__ __nv_bfloat16 sB[128 * SSTR];

    int bx = blockIdx.x, by = blockIdx.y;
    int tid  = threadIdx.x;
    int wid  = tid >> 5, lane = tid & 31;
    int warp_m = wid & 1;     // 0..1  -> 64-row slab
    int warp_n = wid >> 1;    // 0..3  -> 32-col slab

    const __nv_bfloat16* Abase = g_reps + (size_t)(by * 128) * D_DIM;
    const __nv_bfloat16* Bbase = g_reps + (size_t)(bx * 128) * D_DIM;

    float acc[4][4][4];
    #pragma unroll
    for (int mi = 0; mi < 4; mi++)
        #pragma unroll
        for (int ni = 0; ni < 4; ni++)
            #pragma unroll
            for (int k = 0; k < 4; k++) acc[mi][ni][k] = 0.0f;

    for (int kt = 0; kt < D_DIM; kt += BK) {
        // cooperative load: 128 rows x 32 cols = 512 uint4 per tile, 2 per thread
        #pragma unroll
        for (int i = 0; i < 2; i++) {
            int item = tid + i * 256;
            int r  = item >> 2;
            int c4 = item & 3;
            uint4 va = *(const uint4*)(Abase + (size_t)r * D_DIM + kt + c4 * 8);
            *(uint4*)(sA + r * SSTR + c4 * 8) = va;
            uint4 vb = *(const uint4*)(Bbase + (size_t)r * D_DIM + kt + c4 * 8);
            *(uint4*)(sB + r * SSTR + c4 * 8) = vb;
        }
        __syncthreads();

        #pragma unroll
        for (int ks = 0; ks < 2; ks++) {
            int kb = ks * 16;
            uint32_t a[4][4];
            #pragma unroll
            for (int mi = 0; mi < 4; mi++) {
                int row = warp_m * 64 + mi * 16 + (lane & 15);
                int col = kb + ((lane >> 4) << 3);
                uint32_t addr = (uint32_t)__cvta_generic_to_shared(sA + row * SSTR + col);
                asm volatile("ldmatrix.sync.aligned.m8n8.x4.shared.b16 {%0,%1,%2,%3}, [%4];"
                             : "=r"(a[mi][0]), "=r"(a[mi][1]), "=r"(a[mi][2]), "=r"(a[mi][3])
                             : "r"(addr));
            }
            uint32_t b[4][2];
            #pragma unroll
            for (int ni = 0; ni < 4; ni++) {
                int row = warp_n * 32 + ni * 8 + (lane & 7);
                int col = kb + (((lane >> 3) & 1) << 3);
                uint32_t addr = (uint32_t)__cvta_generic_to_shared(sB + row * SSTR + col);
                asm volatile("ldmatrix.sync.aligned.m8n8.x2.shared.b16 {%0,%1}, [%2];"
                             : "=r"(b[ni][0]), "=r"(b[ni][1])
                             : "r"(addr));
            }
            #pragma unroll
            for (int mi = 0; mi < 4; mi++)
                #pragma unroll
                for (int ni = 0; ni < 4; ni++)
                    asm volatile(
                        "mma.sync.aligned.m16n8k16.row.col.f32.bf16.bf16.f32 "
                        "{%0,%1,%2,%3}, {%4,%5,%6,%7}, {%8,%9}, {%0,%1,%2,%3};"
                        : "+f"(acc[mi][ni][0]), "+f"(acc[mi][ni][1]),
                          "+f"(acc[mi][ni][2]), "+f"(acc[mi][ni][3])
                        : "r"(a[mi][0]), "r"(a[mi][1]), "r"(a[mi][2]), "r"(a[mi][3]),
                          "r"(b[ni][0]), "r"(b[ni][1]));
        }
        __syncthreads();
    }

    // Epilogue: exp(2*sim) with diagonal masked, reduce to row sums
    int grow_base = by * 128 + warp_m * 64;
    int gcol_base = bx * 128 + warp_n * 32;
    int lr = lane >> 2;
    int lc = (lane & 3) * 2;

    #pragma unroll
    for (int mi = 0; mi < 4; mi++) {
        int r0 = grow_base + mi * 16 + lr;
        int r1 = r0 + 8;
        float s0 = 0.0f, s1 = 0.0f;
        #pragma unroll
        for (int ni = 0; ni < 4; ni++) {
            int c0 = gcol_base + ni * 8 + lc;
            const float* v = acc[mi][ni];
            if (r0 != c0)     s0 += __expf(v[0] * INV_T);
            if (r0 != c0 + 1) s0 += __expf(v[1] * INV_T);
            if (r1 != c0)     s1 += __expf(v[2] * INV_T);
            if (r1 != c0 + 1) s1 += __expf(v[3] * INV_T);
        }
        // reduce across the 4 lanes that share the same row (lane%4 varies)
        s0 += __shfl_xor_sync(0xFFFFFFFFu, s0, 1);
        s0 += __shfl_xor_sync(0xFFFFFFFFu, s0, 2);
        s1 += __shfl_xor_sync(0xFFFFFFFFu, s1, 1);
        s1 += __shfl_xor_sync(0xFFFFFFFFu, s1, 2);
        if ((lane & 3) == 0) {
            atomicAdd(&g_rowsum[r0], s0);
            atomicAdd(&g_rowsum[r1], s1);
        }
    }
}

// ---------------------------------------------------------------------------
// Kernel 3: per-row positive dot + log(denominator), reduce to scalar loss
// ---------------------------------------------------------------------------
__global__ void finalize_kernel(float* __restrict__ out)
{
    int wid  = threadIdx.x >> 5;
    int lane = threadIdx.x & 31;
    int r = blockIdx.x * 8 + wid;                       // 1024 blocks x 8 warps
    int partner = (r < B_ROWS) ? (r + B_ROWS) : (r - B_ROWS);

    const __nv_bfloat16* zr = g_reps + (size_t)r * D_DIM;
    const __nv_bfloat16* zp = g_reps + (size_t)partner * D_DIM;

    float dot = 0.0f;
    #pragma unroll
    for (int i = 0; i < 4; i++) {
        int c = (lane * 4 + i) * 8;                     // 32 bf16 per lane
        uint4 ua = *(const uint4*)(zr + c);
        uint4 ub = *(const uint4*)(zp + c);
        const __nv_bfloat162* pa = (const __nv_bfloat162*)&ua;
        const __nv_bfloat162* pb = (const __nv_bfloat162*)&ub;
        #pragma unroll
        for (int j = 0; j < 4; j++) {
            float2 fa = __bfloat1622float2(pa[j]);
            float2 fb = __bfloat1622float2(pb[j]);
            dot += fa.x * fb.x + fa.y * fb.y;
        }
    }
    #pragma unroll
    for (int o = 16; o; o >>= 1) dot += __shfl_xor_sync(0xFFFFFFFFu, dot, o);

    if (lane == 0) {
        float lp = logf(g_rowsum[r]) - dot * INV_T;     // -log(exp(pos/T)/denom)
        atomicAdd(out, lp * (1.0f / (float)N2));
    }
}

// ---------------------------------------------------------------------------
extern "C" void kernel_launch(void* const* d_in, const int* in_sizes, int n_in,
                              void* d_out, int out_size)
{
    const float* emb_i = (const float*)d_in[0];
    const float* emb_j = (const float*)d_in[1];
    float* out = (float*)d_out;

    normalize_kernel<<<N2, 256>>>(emb_i, emb_j, out);

    dim3 grid(64, 64);
    simexp_kernel<<<grid, 256>>>();

    finalize_kernel<<<1024, 256>>>(out);
}

// round 3
// speedup vs baseline: 2.4994x; 2.4994x over previous
#include <cuda_runtime.h>
#include <cuda_bf16.h>
#include <cstdint>
#include <cstddef>

#define B_ROWS 4096
#define D_DIM  1024
#define N2     8192        // 2B
#define INV_T  2.0f        // 1/temperature
#define NT     64          // 128-wide tiles per dimension
#define TT     (NT*(NT+1)/2)   // 2080 upper-triangular tiles

// Scratch (device globals; no allocation allowed)
__device__ __nv_bfloat16 g_reps[(size_t)N2 * D_DIM];   // normalized reps, bf16
__device__ float         g_rowsum[N2];                 // sum_{c != r} exp(sim[r][c]/T)

// ---------------------------------------------------------------------------
// Kernel 1: L2-normalize rows of emb_i / emb_j into bf16 reps; zero accumulators
// ---------------------------------------------------------------------------
__global__ void normalize_kernel(const float* __restrict__ emb_i,
                                 const float* __restrict__ emb_j,
                                 float* __restrict__ out)
{
    int row = blockIdx.x;                       // 0..8191
    const float* src = (row < B_ROWS) ? (emb_i + (size_t)row * D_DIM)
                                      : (emb_j + (size_t)(row - B_ROWS) * D_DIM);
    int t = threadIdx.x;                        // 256 threads, 4 floats each
    float4 v = ((const float4*)src)[t];
    float ss = v.x * v.x + v.y * v.y + v.z * v.z + v.w * v.w;

    #pragma unroll
    for (int o = 16; o; o >>= 1) ss += __shfl_xor_sync(0xFFFFFFFFu, ss, o);

    __shared__ float warp_ss[8];
    if ((t & 31) == 0) warp_ss[t >> 5] = ss;
    __syncthreads();
    if (t < 32) {
        float s = (t < 8) ? warp_ss[t] : 0.0f;
        #pragma unroll
        for (int o = 4; o; o >>= 1) s += __shfl_xor_sync(0xFFFFFFFFu, s, o);
        if (t == 0) warp_ss[0] = s;
    }
    __syncthreads();

    float norm = sqrtf(warp_ss[0]);
    float rinv = 1.0f / fmaxf(norm, 1e-12f);

    __nv_bfloat162* dst = (__nv_bfloat162*)(g_reps + (size_t)row * D_DIM);
    dst[t * 2 + 0] = __float22bfloat162_rn(make_float2(v.x * rinv, v.y * rinv));
    dst[t * 2 + 1] = __float22bfloat162_rn(make_float2(v.z * rinv, v.w * rinv));

    // zero rowsum (8192 floats) and output scalar
    if (blockIdx.x < 32) g_rowsum[blockIdx.x * 256 + t] = 0.0f;
    if (blockIdx.x == 0 && t == 0) out[0] = 0.0f;
}

// ---------------------------------------------------------------------------
// Kernel 2: fused  exp(2 * Z Z^T)  row-sum, upper-triangular tiles only.
// Off-diagonal tiles feed BOTH rowsum[r] (row reduce) and rowsum[c] (col reduce).
// CTA tile 128x128, BK=32, 2-stage cp.async pipeline, mma.m16n8k16 bf16.
// ---------------------------------------------------------------------------
#define BK    32
#define NKT   (D_DIM / BK)   // 32 k-steps
#define SSTR  40             // padded smem row stride (bf16); 80B rows, 16B-aligned

__global__ __launch_bounds__(256, 2)
void simexp_kernel()
{
    __shared__ __nv_bfloat16 sA[2][128 * SSTR];
    __shared__ __nv_bfloat16 sB[2][128 * SSTR];

    // decode linear tile index -> (by, bx) with bx >= by
    int idx = blockIdx.x;
    int by = (int)((2.0f * NT + 1.0f - sqrtf((float)((2 * NT + 1) * (2 * NT + 1) - 8 * idx))) * 0.5f);
    while ((by * (2 * NT - by + 1)) / 2 > idx) by--;
    while (((by + 1) * (2 * NT - by)) / 2 <= idx) by++;
    int bx = by + idx - (by * (2 * NT - by + 1)) / 2;

    int tid  = threadIdx.x;
    int wid  = tid >> 5, lane = tid & 31;
    int warp_m = wid & 1;     // 0..1  -> 64-row slab
    int warp_n = wid >> 1;    // 0..3  -> 32-col slab

    const __nv_bfloat16* Abase = g_reps + (size_t)(by * 128) * D_DIM;
    const __nv_bfloat16* Bbase = g_reps + (size_t)(bx * 128) * D_DIM;

    // cooperative cp.async load of one 128x32 stage for A and B
    int l_r  = tid >> 2;          // 0..63 base row (2 items per thread => +64)
    int l_c4 = tid & 3;           // 16B chunk within the 32-col slab

    #define LOAD_STAGE(kt, st)                                                        \
    {                                                                                 \
        _Pragma("unroll")                                                             \
        for (int i = 0; i < 2; i++) {                                                 \
            int r = l_r + i * 64;                                                     \
            const __nv_bfloat16* ga = Abase + (size_t)r * D_DIM + (kt) + l_c4 * 8;    \
            uint32_t da = (uint32_t)__cvta_generic_to_shared(                         \
                              &sA[st][r * SSTR + l_c4 * 8]);                          \
            asm volatile("cp.async.cg.shared.global [%0], [%1], 16;" ::               \
                         "r"(da), "l"(ga));                                           \
            const __nv_bfloat16* gb = Bbase + (size_t)r * D_DIM + (kt) + l_c4 * 8;    \
            uint32_t db = (uint32_t)__cvta_generic_to_shared(                         \
                              &sB[st][r * SSTR + l_c4 * 8]);                          \
            asm volatile("cp.async.cg.shared.global [%0], [%1], 16;" ::               \
                         "r"(db), "l"(gb));                                           \
        }                                                                             \
        asm volatile("cp.async.commit_group;");                                       \
    }

    float acc[4][4][4];
    #pragma unroll
    for (int mi = 0; mi < 4; mi++)
        #pragma unroll
        for (int ni = 0; ni < 4; ni++)
            #pragma unroll
            for (int k = 0; k < 4; k++) acc[mi][ni][k] = 0.0f;

    LOAD_STAGE(0, 0);

    for (int kt = 0; kt < NKT; kt++) {
        int st = kt & 1;
        if (kt + 1 < NKT) {
            LOAD_STAGE((kt + 1) * BK, (kt + 1) & 1);
            asm volatile("cp.async.wait_group 1;");
        } else {
            asm volatile("cp.async.wait_group 0;");
        }
        __syncthreads();

        #pragma unroll
        for (int ks = 0; ks < 2; ks++) {
            int kb = ks * 16;
            uint32_t a[4][4];
            #pragma unroll
            for (int mi = 0; mi < 4; mi++) {
                int row = warp_m * 64 + mi * 16 + (lane & 15);
                int col = kb + ((lane >> 4) << 3);
                uint32_t addr = (uint32_t)__cvta_generic_to_shared(&sA[st][row * SSTR + col]);
                asm volatile("ldmatrix.sync.aligned.m8n8.x4.shared.b16 {%0,%1,%2,%3}, [%4];"
                             : "=r"(a[mi][0]), "=r"(a[mi][1]), "=r"(a[mi][2]), "=r"(a[mi][3])
                             : "r"(addr));
            }
            uint32_t b[4][2];
            #pragma unroll
            for (int ni = 0; ni < 4; ni++) {
                int row = warp_n * 32 + ni * 8 + (lane & 7);
                int col = kb + (((lane >> 3) & 1) << 3);
                uint32_t addr = (uint32_t)__cvta_generic_to_shared(&sB[st][row * SSTR + col]);
                asm volatile("ldmatrix.sync.aligned.m8n8.x2.shared.b16 {%0,%1}, [%2];"
                             : "=r"(b[ni][0]), "=r"(b[ni][1])
                             : "r"(addr));
            }
            #pragma unroll
            for (int mi = 0; mi < 4; mi++)
                #pragma unroll
                for (int ni = 0; ni < 4; ni++)
                    asm volatile(
                        "mma.sync.aligned.m16n8k16.row.col.f32.bf16.bf16.f32 "
                        "{%0,%1,%2,%3}, {%4,%5,%6,%7}, {%8,%9}, {%0,%1,%2,%3};"
                        : "+f"(acc[mi][ni][0]), "+f"(acc[mi][ni][1]),
                          "+f"(acc[mi][ni][2]), "+f"(acc[mi][ni][3])
                        : "r"(a[mi][0]), "r"(a[mi][1]), "r"(a[mi][2]), "r"(a[mi][3]),
                          "r"(b[ni][0]), "r"(b[ni][1]));
        }
        __syncthreads();
    }

    // ---------------- Epilogue ----------------
    int grow_base = by * 128 + warp_m * 64;
    int gcol_base = bx * 128 + warp_n * 32;
    int lr = lane >> 2;
    int lc = (lane & 3) * 2;
    bool offdiag = (bx != by);

    float colacc[4][2];
    #pragma unroll
    for (int ni = 0; ni < 4; ni++) { colacc[ni][0] = 0.0f; colacc[ni][1] = 0.0f; }

    #pragma unroll
    for (int mi = 0; mi < 4; mi++) {
        int r0 = grow_base + mi * 16 + lr;
        int r1 = r0 + 8;
        float s0 = 0.0f, s1 = 0.0f;
        #pragma unroll
        for (int ni = 0; ni < 4; ni++) {
            int c0 = gcol_base + ni * 8 + lc;
            const float* v = acc[mi][ni];
            float e00 = (r0 != c0)     ? __expf(v[0] * INV_T) : 0.0f;
            float e01 = (r0 != c0 + 1) ? __expf(v[1] * INV_T) : 0.0f;
            float e10 = (r1 != c0)     ? __expf(v[2] * INV_T) : 0.0f;
            float e11 = (r1 != c0 + 1) ? __expf(v[3] * INV_T) : 0.0f;
            s0 += e00 + e01;
            s1 += e10 + e11;
            colacc[ni][0] += e00 + e10;
            colacc[ni][1] += e01 + e11;
        }
        // reduce rows across the 4 lanes sharing the same row (lane&3 varies)
        s0 += __shfl_xor_sync(0xFFFFFFFFu, s0, 1);
        s0 += __shfl_xor_sync(0xFFFFFFFFu, s0, 2);
        s1 += __shfl_xor_sync(0xFFFFFFFFu, s1, 1);
        s1 += __shfl_xor_sync(0xFFFFFFFFu, s1, 2);
        if ((lane & 3) == 0) {
            atomicAdd(&g_rowsum[r0], s0);
            atomicAdd(&g_rowsum[r1], s1);
        }
    }

    if (offdiag) {
        // column sums: reduce across the 8 lanes sharing the same column pair
        #pragma unroll
        for (int ni = 0; ni < 4; ni++) {
            float c0 = colacc[ni][0], c1 = colacc[ni][1];
            #pragma unroll
            for (int o = 4; o <= 16; o <<= 1) {
                c0 += __shfl_xor_sync(0xFFFFFFFFu, c0, o);
                c1 += __shfl_xor_sync(0xFFFFFFFFu, c1, o);
            }
            if (lane < 4) {
                int c = gcol_base + ni * 8 + lane * 2;
                atomicAdd(&g_rowsum[c],     c0);
                atomicAdd(&g_rowsum[c + 1], c1);
            }
        }
    }
}

// ---------------------------------------------------------------------------
// Kernel 3: per-row positive dot + log(denominator), reduce to scalar loss
// ---------------------------------------------------------------------------
__global__ void finalize_kernel(float* __restrict__ out)
{
    int wid  = threadIdx.x >> 5;
    int lane = threadIdx.x & 31;
    int r = blockIdx.x * 8 + wid;                       // 1024 blocks x 8 warps
    int partner = (r < B_ROWS) ? (r + B_ROWS) : (r - B_ROWS);

    const __nv_bfloat16* zr = g_reps + (size_t)r * D_DIM;
    const __nv_bfloat16* zp = g_reps + (size_t)partner * D_DIM;

    float dot = 0.0f;
    #pragma unroll
    for (int i = 0; i < 4; i++) {
        int c = (lane * 4 + i) * 8;                     // 32 bf16 per lane
        uint4 ua = *(const uint4*)(zr + c);
        uint4 ub = *(const uint4*)(zp + c);
        const __nv_bfloat162* pa = (const __nv_bfloat162*)&ua;
        const __nv_bfloat162* pb = (const __nv_bfloat162*)&ub;
        #pragma unroll
        for (int j = 0; j < 4; j++) {
            float2 fa = __bfloat1622float2(pa[j]);
            float2 fb = __bfloat1622float2(pb[j]);
            dot += fa.x * fb.x + fa.y * fb.y;
        }
    }
    #pragma unroll
    for (int o = 16; o; o >>= 1) dot += __shfl_xor_sync(0xFFFFFFFFu, dot, o);

    if (lane == 0) {
        float lp = logf(g_rowsum[r]) - dot * INV_T;     // -log(exp(pos/T)/denom)
        atomicAdd(out, lp * (1.0f / (float)N2));
    }
}

// ---------------------------------------------------------------------------
extern "C" void kernel_launch(void* const* d_in, const int* in_sizes, int n_in,
                              void* d_out, int out_size)
{
    const float* emb_i = (const float*)d_in[0];
    const float* emb_j = (const float*)d_in[1];
    float* out = (float*)d_out;

    normalize_kernel<<<N2, 256>>>(emb_i, emb_j, out);
    simexp_kernel<<<TT, 256>>>();
    finalize_kernel<<<1024, 256>>>(out);
}

// round 5
// speedup vs baseline: 2.7800x; 1.1123x over previous
#include <cuda_runtime.h>
#include <cuda_bf16.h>
#include <cuda_fp8.h>
#include <cstdint>
#include <cstddef>

#define B_ROWS 4096
#define D_DIM  1024
#define N2     8192
#define INV_T  2.0f
#define NT     64                  // 128-wide tiles per dimension
#define TT     (NT*(NT+1)/2)       // 2080 upper-triangular tiles

// Scratch (device globals; no allocation allowed)
__device__ uint8_t       g_reps8[(size_t)N2 * D_DIM];  // normalized reps, e4m3 (GEMM)
__device__ __nv_bfloat16 g_repsb[(size_t)N2 * D_DIM];  // normalized reps, bf16 (positives)
__device__ float         g_rowsum[N2];

// ---------------------------------------------------------------------------
// Kernel 1: L2-normalize rows; write e4m3 + bf16 reps; zero accumulators
// ---------------------------------------------------------------------------
__global__ void normalize_kernel(const float* __restrict__ emb_i,
                                 const float* __restrict__ emb_j,
                                 float* __restrict__ out)
{
    int row = blockIdx.x;                       // 0..8191
    const float* src = (row < B_ROWS) ? (emb_i + (size_t)row * D_DIM)
                                      : (emb_j + (size_t)(row - B_ROWS) * D_DIM);
    int t = threadIdx.x;                        // 256 threads, 4 floats each
    float4 v = ((const float4*)src)[t];
    float ss = v.x * v.x + v.y * v.y + v.z * v.z + v.w * v.w;

    #pragma unroll
    for (int o = 16; o; o >>= 1) ss += __shfl_xor_sync(0xFFFFFFFFu, ss, o);

    __shared__ float warp_ss[8];
    if ((t & 31) == 0) warp_ss[t >> 5] = ss;
    __syncthreads();
    if (t < 32) {
        float s = (t < 8) ? warp_ss[t] : 0.0f;
        #pragma unroll
        for (int o = 4; o; o >>= 1) s += __shfl_xor_sync(0xFFFFFFFFu, s, o);
        if (t == 0) warp_ss[0] = s;
    }
    __syncthreads();

    float rinv = 1.0f / fmaxf(sqrtf(warp_ss[0]), 1e-12f);
    float nx = v.x * rinv, ny = v.y * rinv, nz = v.z * rinv, nw = v.w * rinv;

    // bf16 copy (for accurate positive dots)
    __nv_bfloat162* dstb = (__nv_bfloat162*)(g_repsb + (size_t)row * D_DIM);
    dstb[t * 2 + 0] = __float22bfloat162_rn(make_float2(nx, ny));
    dstb[t * 2 + 1] = __float22bfloat162_rn(make_float2(nz, nw));

    // e4m3 copy (for the big GEMM)
    __nv_fp8x2_e4m3 p0(make_float2(nx, ny));
    __nv_fp8x2_e4m3 p1(make_float2(nz, nw));
    uint32_t packed = (uint32_t)*(uint16_t*)&p0 | ((uint32_t)*(uint16_t*)&p1 << 16);
    ((uint32_t*)(g_reps8 + (size_t)row * D_DIM))[t] = packed;

    if (blockIdx.x < 32) g_rowsum[blockIdx.x * 256 + t] = 0.0f;
    if (blockIdx.x == 0 && t == 0) out[0] = 0.0f;
}

// ---------------------------------------------------------------------------
// Kernel 2: fused exp(2 * Z Z^T) row-sum, upper-triangular tiles, FP8 QMMA.
// Off-diagonal tiles feed BOTH rowsum[r] and rowsum[c].
// CTA tile 128x128, BK=64 fp8 (64B rows), 2-stage cp.async, mma.m16n8k32.e4m3.
// ---------------------------------------------------------------------------
#define BK    64                  // fp8 elems (=bytes) per k-stage
#define NKT   (D_DIM / BK)        // 16 k-stages
#define SSTR  80                  // padded smem row stride in BYTES (64 + 16)

__global__ __launch_bounds__(256, 2)
void simexp_kernel()
{
    __shared__ uint8_t sA[2][128 * SSTR];
    __shared__ uint8_t sB[2][128 * SSTR];

    // decode linear tile index -> (by, bx) with bx >= by
    int idx = blockIdx.x;
    int by = (int)((2.0f * NT + 1.0f
              - sqrtf((float)((2 * NT + 1) * (2 * NT + 1) - 8 * idx))) * 0.5f);
    while ((by * (2 * NT - by + 1)) / 2 > idx) by--;
    while (((by + 1) * (2 * NT - by)) / 2 <= idx) by++;
    int bx = by + idx - (by * (2 * NT - by + 1)) / 2;
    bool offdiag = (bx != by);

    int tid  = threadIdx.x;
    int wid  = tid >> 5, lane = tid & 31;
    int warp_m = wid & 1;     // 0..1  -> 64-row slab
    int warp_n = wid >> 1;    // 0..3  -> 32-col slab

    const uint8_t* Abase = g_reps8 + (size_t)(by * 128) * D_DIM;
    const uint8_t* Bbase = g_reps8 + (size_t)(bx * 128) * D_DIM;

    // cooperative cp.async: 128 rows x 64B per matrix = 512 16B-chunks, 2/thread
    int l_r  = tid >> 2;          // base row 0..63 (second item: +64)
    int l_c4 = tid & 3;           // 16B chunk within the 64B slab

    #define LOAD_STAGE(kt, st)                                                        \
    {                                                                                 \
        _Pragma("unroll")                                                             \
        for (int i = 0; i < 2; i++) {                                                 \
            int r = l_r + i * 64;                                                     \
            const uint8_t* ga = Abase + (size_t)r * D_DIM + (kt) + l_c4 * 16;         \
            uint32_t da = (uint32_t)__cvta_generic_to_shared(                         \
                              &sA[st][r * SSTR + l_c4 * 16]);                         \
            asm volatile("cp.async.cg.shared.global [%0], [%1], 16;" ::               \
                         "r"(da), "l"(ga));                                           \
            const uint8_t* gb = Bbase + (size_t)r * D_DIM + (kt) + l_c4 * 16;         \
            uint32_t db = (uint32_t)__cvta_generic_to_shared(                         \
                              &sB[st][r * SSTR + l_c4 * 16]);                         \
            asm volatile("cp.async.cg.shared.global [%0], [%1], 16;" ::               \
                         "r"(db), "l"(gb));                                           \
        }                                                                             \
        asm volatile("cp.async.commit_group;");                                       \
    }

    float acc[4][4][4];
    #pragma unroll
    for (int mi = 0; mi < 4; mi++)
        #pragma unroll
        for (int ni = 0; ni < 4; ni++)
            #pragma unroll
            for (int k = 0; k < 4; k++) acc[mi][ni][k] = 0.0f;

    LOAD_STAGE(0, 0);

    for (int kt = 0; kt < NKT; kt++) {
        int st = kt & 1;
        if (kt + 1 < NKT) {
            LOAD_STAGE((kt + 1) * BK, (kt + 1) & 1);
            asm volatile("cp.async.wait_group 1;");
        } else {
            asm volatile("cp.async.wait_group 0;");
        }
        __syncthreads();

        #pragma unroll
        for (int ks = 0; ks < 2; ks++) {
            int kb = ks * 32;                            // byte offset of k32 chunk
            uint32_t a[4][4];
            #pragma unroll
            for (int mi = 0; mi < 4; mi++) {
                int row = warp_m * 64 + mi * 16 + (lane & 15);
                int col = kb + ((lane >> 4) << 4);       // 0 / 16 bytes
                uint32_t addr = (uint32_t)__cvta_generic_to_shared(&sA[st][row * SSTR + col]);
                asm volatile("ldmatrix.sync.aligned.m8n8.x4.shared.b16 {%0,%1,%2,%3}, [%4];"
                             : "=r"(a[mi][0]), "=r"(a[mi][1]), "=r"(a[mi][2]), "=r"(a[mi][3])
                             : "r"(addr));
            }
            uint32_t b[4][2];
            #pragma unroll
            for (int ni = 0; ni < 4; ni++) {
                int row = warp_n * 32 + ni * 8 + (lane & 7);
                int col = kb + (((lane >> 3) & 1) << 4); // 0 / 16 bytes
                uint32_t addr = (uint32_t)__cvta_generic_to_shared(&sB[st][row * SSTR + col]);
                asm volatile("ldmatrix.sync.aligned.m8n8.x2.shared.b16 {%0,%1}, [%2];"
                             : "=r"(b[ni][0]), "=r"(b[ni][1])
                             : "r"(addr));
            }
            #pragma unroll
            for (int mi = 0; mi < 4; mi++)
                #pragma unroll
                for (int ni = 0; ni < 4; ni++)
                    asm volatile(
                        "mma.sync.aligned.m16n8k32.row.col.f32.e4m3.e4m3.f32 "
                        "{%0,%1,%2,%3}, {%4,%5,%6,%7}, {%8,%9}, {%0,%1,%2,%3};"
                        : "+f"(acc[mi][ni][0]), "+f"(acc[mi][ni][1]),
                          "+f"(acc[mi][ni][2]), "+f"(acc[mi][ni][3])
                        : "r"(a[mi][0]), "r"(a[mi][1]), "r"(a[mi][2]), "r"(a[mi][3]),
                          "r"(b[ni][0]), "r"(b[ni][1]));
        }
        __syncthreads();
    }

    // ---------------- Epilogue ----------------
    int grow_base = by * 128 + warp_m * 64;
    int gcol_base = bx * 128 + warp_n * 32;
    int lr = lane >> 2;
    int lc = (lane & 3) * 2;

    float colacc[4][2];
    #pragma unroll
    for (int ni = 0; ni < 4; ni++) { colacc[ni][0] = 0.0f; colacc[ni][1] = 0.0f; }

    #pragma unroll
    for (int mi = 0; mi < 4; mi++) {
        int r0 = grow_base + mi * 16 + lr;
        int r1 = r0 + 8;
        float s0 = 0.0f, s1 = 0.0f;
        #pragma unroll
        for (int ni = 0; ni < 4; ni++) {
            int c0 = gcol_base + ni * 8 + lc;
            const float* v = acc[mi][ni];
            float e00 = (r0 != c0)     ? __expf(v[0] * INV_T) : 0.0f;
            float e01 = (r0 != c0 + 1) ? __expf(v[1] * INV_T) : 0.0f;
            float e10 = (r1 != c0)     ? __expf(v[2] * INV_T) : 0.0f;
            float e11 = (r1 != c0 + 1) ? __expf(v[3] * INV_T) : 0.0f;
            s0 += e00 + e01;
            s1 += e10 + e11;
            colacc[ni][0] += e00 + e10;
            colacc[ni][1] += e01 + e11;
        }
        s0 += __shfl_xor_sync(0xFFFFFFFFu, s0, 1);
        s0 += __shfl_xor_sync(0xFFFFFFFFu, s0, 2);
        s1 += __shfl_xor_sync(0xFFFFFFFFu, s1, 1);
        s1 += __shfl_xor_sync(0xFFFFFFFFu, s1, 2);
        if ((lane & 3) == 0) {
            atomicAdd(&g_rowsum[r0], s0);
            atomicAdd(&g_rowsum[r1], s1);
        }
    }

    if (offdiag) {
        #pragma unroll
        for (int ni = 0; ni < 4; ni++) {
            float c0 = colacc[ni][0], c1 = colacc[ni][1];
            #pragma unroll
            for (int o = 4; o <= 16; o <<= 1) {
                c0 += __shfl_xor_sync(0xFFFFFFFFu, c0, o);
                c1 += __shfl_xor_sync(0xFFFFFFFFu, c1, o);
            }
            if (lane < 4) {
                int c = gcol_base + ni * 8 + lane * 2;
                atomicAdd(&g_rowsum[c],     c0);
                atomicAdd(&g_rowsum[c + 1], c1);
            }
        }
    }
}

// ---------------------------------------------------------------------------
// Kernel 3: per-row positive dot (bf16) + log(denominator), scalar reduce
// ---------------------------------------------------------------------------
__global__ void finalize_kernel(float* __restrict__ out)
{
    int wid  = threadIdx.x >> 5;
    int lane = threadIdx.x & 31;
    int r = blockIdx.x * 8 + wid;
    int partner = (r < B_ROWS) ? (r + B_ROWS) : (r - B_ROWS);

    const __nv_bfloat16* zr = g_repsb + (size_t)r * D_DIM;
    const __nv_bfloat16* zp = g_repsb + (size_t)partner * D_DIM;

    float dot = 0.0f;
    #pragma unroll
    for (int i = 0; i < 4; i++) {
        int c = (lane * 4 + i) * 8;
        uint4 ua = *(const uint4*)(zr + c);
        uint4 ub = *(const uint4*)(zp + c);
        const __nv_bfloat162* pa = (const __nv_bfloat162*)&ua;
        const __nv_bfloat162* pb = (const __nv_bfloat162*)&ub;
        #pragma unroll
        for (int j = 0; j < 4; j++) {
            float2 fa = __bfloat1622float2(pa[j]);
            float2 fb = __bfloat1622float2(pb[j]);
            dot += fa.x * fb.x + fa.y * fb.y;
        }
    }
    #pragma unroll
    for (int o = 16; o; o >>= 1) dot += __shfl_xor_sync(0xFFFFFFFFu, dot, o);

    if (lane == 0) {
        float lp = logf(g_rowsum[r]) - dot * INV_T;
        atomicAdd(out, lp * (1.0f / (float)N2));
    }
}

// ---------------------------------------------------------------------------
extern "C" void kernel_launch(void* const* d_in, const int* in_sizes, int n_in,
                              void* d_out, int out_size)
{
    const float* emb_i = (const float*)d_in[0];
    const float* emb_j = (const float*)d_in[1];
    float* out = (float*)d_out;

    normalize_kernel<<<N2, 256>>>(emb_i, emb_j, out);
    simexp_kernel<<<TT, 256>>>();
    finalize_kernel<<<1024, 256>>>(out);
}